// round 1
// baseline (speedup 1.0000x reference)
#include <cuda_runtime.h>
#include <math.h>
#include <float.h>

#define NC   4096   // number of clouds (8*512)
#define NP   32     // points per cloud
#define KNB  8      // neighbors
#define C1   64
#define C2   128
#define S1   68     // padded smem row stride for C1 arrays
#define S2   132    // padded smem row stride for C2 arrays
#define ECH  384

// ---- shared memory layout (float words) ----
#define OFF_W2   0                         // 16384
#define OFF_P2   (OFF_W2 + 16384)          // 32*132 = 4224
#define OFF_Q2   (OFF_P2 + 4224)
#define OFF_F2   (OFF_Q2 + 4224)
#define OFF_P1   (OFF_F2 + 4224)           // 32*68 = 2176
#define OFF_Q1   (OFF_P1 + 2176)
#define OFF_F1   (OFF_Q1 + 2176)
#define OFF_W1   (OFF_F1 + 2176)           // 384
#define OFF_B1   (OFF_W1 + 384)            // 64
#define OFF_G1   (OFF_B1 + 64)
#define OFF_BE1  (OFF_G1 + 64)
#define OFF_B2   (OFF_BE1 + 64)            // 128
#define OFF_G2   (OFF_B2 + 128)
#define OFF_BE2  (OFF_G2 + 128)
#define OFF_XS   (OFF_BE2 + 128)           // 96
#define OFF_IDX  (OFF_XS + 96)             // 256 ints
#define SMEM1_WORDS (OFF_IDX + 256)
#define SMEM1_BYTES (SMEM1_WORDS * 4)      // 147584

#define SMEM2_BYTES ((64*128 + 128*128) * 4)  // 98304

__device__ float g_pool[NC * C2];

__device__ __forceinline__ float elu_f(float x) {
    return x > 0.f ? x : (__expf(x) - 1.f);
}

// Edge phase: for each of 256 edges (i,k), t_j = U[i][j] + V[nbr][j]
// (bias folded into U). LayerNorm over j, ELU, max over the 8 edges of
// each point i (8 consecutive lanes), leader writes F[i][:].
template<int NCH, int STRIDE>
__device__ __forceinline__ void edge_phase(
    const float* __restrict__ U, const float* __restrict__ V,
    float* __restrict__ F, const float* __restrict__ g,
    const float* __restrict__ be, const int* __restrict__ idxs,
    float invC, int tid)
{
    const int i = tid >> 3;
    const int k = tid & 7;
    const int n = idxs[i * KNB + k];
    const float4* u4 = reinterpret_cast<const float4*>(U + i * STRIDE);
    const float4* v4 = reinterpret_cast<const float4*>(V + n * STRIDE);

    float s = 0.f, ss = 0.f;
#pragma unroll 8
    for (int jj = 0; jj < NCH; jj++) {
        float4 u = u4[jj], v = v4[jj];
        float t0 = u.x + v.x, t1 = u.y + v.y, t2 = u.z + v.z, t3 = u.w + v.w;
        s += (t0 + t1) + (t2 + t3);
        ss = fmaf(t0, t0, ss); ss = fmaf(t1, t1, ss);
        ss = fmaf(t2, t2, ss); ss = fmaf(t3, t3, ss);
    }
    float mu = s * invC;
    float var = fmaxf(fmaf(-mu, mu, ss * invC), 0.f);
    float rstd = rsqrtf(var + 1e-5f);

    const float4* g4 = reinterpret_cast<const float4*>(g);
    const float4* be4 = reinterpret_cast<const float4*>(be);
    float4* Fo = reinterpret_cast<float4*>(F + i * STRIDE);

#pragma unroll 8
    for (int jj = 0; jj < NCH; jj++) {
        float4 u = u4[jj], v = v4[jj];
        float4 gg = g4[jj], bb = be4[jj];
        float e0 = elu_f(fmaf((u.x + v.x - mu) * rstd, gg.x, bb.x));
        float e1 = elu_f(fmaf((u.y + v.y - mu) * rstd, gg.y, bb.y));
        float e2 = elu_f(fmaf((u.z + v.z - mu) * rstd, gg.z, bb.z));
        float e3 = elu_f(fmaf((u.w + v.w - mu) * rstd, gg.w, bb.w));
#pragma unroll
        for (int off = 1; off < 8; off <<= 1) {
            e0 = fmaxf(e0, __shfl_xor_sync(0xffffffffu, e0, off));
            e1 = fmaxf(e1, __shfl_xor_sync(0xffffffffu, e1, off));
            e2 = fmaxf(e2, __shfl_xor_sync(0xffffffffu, e2, off));
            e3 = fmaxf(e3, __shfl_xor_sync(0xffffffffu, e3, off));
        }
        if (k == 0) Fo[jj] = make_float4(e0, e1, e2, e3);
    }
}

__global__ __launch_bounds__(256, 1)
void knn_encoder_kernel(
    const float* __restrict__ x,
    const float* __restrict__ W1, const float* __restrict__ b1,
    const float* __restrict__ g1, const float* __restrict__ be1,
    const float* __restrict__ W2, const float* __restrict__ b2,
    const float* __restrict__ g2, const float* __restrict__ be2)
{
    extern __shared__ float sm[];
    int* idxs = reinterpret_cast<int*>(sm + OFF_IDX);
    const int tid = threadIdx.x;
    const int cloud = blockIdx.x;
    const float* xg = x + cloud * NP * 3;

    // ---- small loads ----
    if (tid < 96)  sm[OFF_XS + tid] = xg[tid];
    if (tid < 64)  { sm[OFF_B1 + tid] = b1[tid]; sm[OFF_G1 + tid] = g1[tid]; sm[OFF_BE1 + tid] = be1[tid]; }
    if (tid < 128) { sm[OFF_B2 + tid] = b2[tid]; sm[OFF_G2 + tid] = g2[tid]; sm[OFF_BE2 + tid] = be2[tid]; }
    for (int t = tid; t < 384; t += 256) sm[OFF_W1 + t] = W1[t];
    __syncthreads();

    // ---- W2 -> smem (overlaps with KNN + conv1 P/Q compute) ----
    {
        const float4* src = reinterpret_cast<const float4*>(W2);
        float4* dst = reinterpret_cast<float4*>(sm + OFF_W2);
#pragma unroll
        for (int r = 0; r < 16; r++) dst[tid + r * 256] = src[tid + r * 256];
    }

    // ---- KNN: warp w handles points {w, w+8, w+16, w+24}; lane = candidate m ----
    {
        const int w = tid >> 5, m = tid & 31;
        const float xm0 = sm[OFF_XS + m * 3 + 0];
        const float xm1 = sm[OFF_XS + m * 3 + 1];
        const float xm2 = sm[OFF_XS + m * 3 + 2];
        const float smq = xm0 * xm0 + xm1 * xm1 + xm2 * xm2;
#pragma unroll
        for (int rep = 0; rep < 4; rep++) {
            const int i = w + rep * 8;
            const float xi0 = sm[OFF_XS + i * 3 + 0];
            const float xi1 = sm[OFF_XS + i * 3 + 1];
            const float xi2 = sm[OFF_XS + i * 3 + 2];
            const float si = xi0 * xi0 + xi1 * xi1 + xi2 * xi2;
            const float dot = xi0 * xm0 + xi1 * xm1 + xi2 * xm2;
            float d2 = si + smq - 2.f * dot;
            for (int r = 0; r < KNB; r++) {
                float v = d2; int mi = m;
#pragma unroll
                for (int off = 16; off; off >>= 1) {
                    float ov = __shfl_xor_sync(0xffffffffu, v, off);
                    int   oi = __shfl_xor_sync(0xffffffffu, mi, off);
                    if (ov < v || (ov == v && oi < mi)) { v = ov; mi = oi; }
                }
                if (m == 0) idxs[i * KNB + r] = mi;   // lowest-index tiebreak = lax.top_k
                if (m == mi) d2 = FLT_MAX;
            }
        }
    }

    // ---- conv1 P/Q: P1[i][j] = b1[j] + x_i . W1[0:3][j], Q1[i][j] = x_i . W1[3:6][j] ----
    for (int o = tid; o < NP * C1; o += 256) {
        const int i = o >> 6, j = o & 63;
        const float x0 = sm[OFF_XS + i * 3 + 0];
        const float x1 = sm[OFF_XS + i * 3 + 1];
        const float x2 = sm[OFF_XS + i * 3 + 2];
        float p = sm[OFF_B1 + j];
        p = fmaf(x0, sm[OFF_W1 + j], p);
        p = fmaf(x1, sm[OFF_W1 + 64 + j], p);
        p = fmaf(x2, sm[OFF_W1 + 128 + j], p);
        float q = x0 * sm[OFF_W1 + 192 + j];
        q = fmaf(x1, sm[OFF_W1 + 256 + j], q);
        q = fmaf(x2, sm[OFF_W1 + 320 + j], q);
        sm[OFF_P1 + i * S1 + j] = p;
        sm[OFF_Q1 + i * S1 + j] = q;
    }
    __syncthreads();

    // ---- edge phase 1 -> f1[32][64] ----
    edge_phase<16, S1>(sm + OFF_P1, sm + OFF_Q1, sm + OFF_F1,
                       sm + OFF_G1, sm + OFF_BE1, idxs, 1.f / 64.f, tid);
    __syncthreads();

    // ---- conv2 P/Q GEMM: P2 = f1 @ W2[0:64] + b2, Q2 = f1 @ W2[64:128] ----
    {
        const int ip = tid >> 4;        // 0..15 -> row pair
        const int jg = tid & 15;        // 0..15 -> 8-col group
        const int i0 = ip * 2, j0 = jg * 8;
        float accP[2][8], accQ[2][8];
#pragma unroll
        for (int r = 0; r < 2; r++)
#pragma unroll
            for (int jj = 0; jj < 8; jj++) { accP[r][jj] = 0.f; accQ[r][jj] = 0.f; }

        const float* F1 = sm + OFF_F1;
        const float* W2s = sm + OFF_W2;
#pragma unroll 4
        for (int c = 0; c < 64; c++) {
            const float a0 = F1[i0 * S1 + c];
            const float a1 = F1[i0 * S1 + S1 + c];
            float wp[8], wq[8];
            *reinterpret_cast<float4*>(wp)     = *reinterpret_cast<const float4*>(W2s + c * 128 + j0);
            *reinterpret_cast<float4*>(wp + 4) = *reinterpret_cast<const float4*>(W2s + c * 128 + j0 + 4);
            *reinterpret_cast<float4*>(wq)     = *reinterpret_cast<const float4*>(W2s + (64 + c) * 128 + j0);
            *reinterpret_cast<float4*>(wq + 4) = *reinterpret_cast<const float4*>(W2s + (64 + c) * 128 + j0 + 4);
#pragma unroll
            for (int jj = 0; jj < 8; jj++) {
                accP[0][jj] = fmaf(a0, wp[jj], accP[0][jj]);
                accP[1][jj] = fmaf(a1, wp[jj], accP[1][jj]);
                accQ[0][jj] = fmaf(a0, wq[jj], accQ[0][jj]);
                accQ[1][jj] = fmaf(a1, wq[jj], accQ[1][jj]);
            }
        }
#pragma unroll
        for (int r = 0; r < 2; r++)
#pragma unroll
            for (int jj = 0; jj < 8; jj++) {
                sm[OFF_P2 + (i0 + r) * S2 + j0 + jj] = accP[r][jj] + sm[OFF_B2 + j0 + jj];
                sm[OFF_Q2 + (i0 + r) * S2 + j0 + jj] = accQ[r][jj];
            }
    }
    __syncthreads();

    // ---- edge phase 2 -> f2[32][128] ----
    edge_phase<32, S2>(sm + OFF_P2, sm + OFF_Q2, sm + OFF_F2,
                       sm + OFF_G2, sm + OFF_BE2, idxs, 1.f / 128.f, tid);
    __syncthreads();

    // ---- mean pool over points -> g_pool[cloud][128] ----
    if (tid < 128) {
        float s = 0.f;
#pragma unroll 8
        for (int i = 0; i < NP; i++) s += sm[OFF_F2 + i * S2 + tid];
        g_pool[cloud * C2 + tid] = s * (1.f / 32.f);
    }
}

// out[4096,384] = g_pool[4096,128] @ Wo[128,384] + bo
__global__ __launch_bounds__(256, 1)
void proj_kernel(const float* __restrict__ Wo, const float* __restrict__ bo,
                 float* __restrict__ out)
{
    extern __shared__ float sm2[];
    float* As = sm2;            // 64 x 128
    float* Ws = sm2 + 64 * 128; // 128 x 128
    const int tid = threadIdx.x;
    const int row0 = blockIdx.x * 64;
    const int colB = blockIdx.y * 128;

    {
        const float4* ag = reinterpret_cast<const float4*>(g_pool + row0 * 128);
        float4* ad = reinterpret_cast<float4*>(As);
#pragma unroll
        for (int r = 0; r < 8; r++) ad[tid + r * 256] = ag[tid + r * 256];
    }
    for (int t = tid; t < 128 * 128; t += 256) {
        const int c = t >> 7, j = t & 127;
        Ws[t] = Wo[c * ECH + colB + j];
    }
    __syncthreads();

    const int r0 = (tid >> 4) * 4;
    const int c0 = (tid & 15) * 8;
    float acc[4][8];
#pragma unroll
    for (int r = 0; r < 4; r++)
#pragma unroll
        for (int cc = 0; cc < 8; cc++) acc[r][cc] = 0.f;

#pragma unroll 4
    for (int c = 0; c < 128; c++) {
        float a[4];
#pragma unroll
        for (int r = 0; r < 4; r++) a[r] = As[(r0 + r) * 128 + c];
        float w[8];
        *reinterpret_cast<float4*>(w)     = *reinterpret_cast<const float4*>(Ws + c * 128 + c0);
        *reinterpret_cast<float4*>(w + 4) = *reinterpret_cast<const float4*>(Ws + c * 128 + c0 + 4);
#pragma unroll
        for (int r = 0; r < 4; r++)
#pragma unroll
            for (int cc = 0; cc < 8; cc++)
                acc[r][cc] = fmaf(a[r], w[cc], acc[r][cc]);
    }
#pragma unroll
    for (int r = 0; r < 4; r++)
#pragma unroll
        for (int cc = 0; cc < 8; cc++)
            out[(row0 + r0 + r) * ECH + colB + c0 + cc] = acc[r][cc] + bo[colB + c0 + cc];
}

extern "C" void kernel_launch(void* const* d_in, const int* in_sizes, int n_in,
                              void* d_out, int out_size)
{
    const float* x   = (const float*)d_in[0];
    const float* W1  = (const float*)d_in[1];
    const float* b1  = (const float*)d_in[2];
    const float* g1  = (const float*)d_in[3];
    const float* be1 = (const float*)d_in[4];
    const float* W2  = (const float*)d_in[5];
    const float* b2  = (const float*)d_in[6];
    const float* g2  = (const float*)d_in[7];
    const float* be2 = (const float*)d_in[8];
    const float* Wo  = (const float*)d_in[9];
    const float* bo  = (const float*)d_in[10];
    float* out = (float*)d_out;

    cudaFuncSetAttribute(knn_encoder_kernel,
                         cudaFuncAttributeMaxDynamicSharedMemorySize, SMEM1_BYTES);
    cudaFuncSetAttribute(proj_kernel,
                         cudaFuncAttributeMaxDynamicSharedMemorySize, SMEM2_BYTES);

    knn_encoder_kernel<<<NC, 256, SMEM1_BYTES>>>(x, W1, b1, g1, be1, W2, b2, g2, be2);
    proj_kernel<<<dim3(64, 3), 256, SMEM2_BYTES>>>(Wo, bo, out);
}

// round 2
// speedup vs baseline: 1.7499x; 1.7499x over previous
#include <cuda_runtime.h>
#include <math.h>
#include <float.h>

#define NC   4096   // number of clouds (8*512)
#define NP   32     // points per cloud
#define KNB  8      // neighbors
#define C1   64
#define C2   128
#define S1   68     // padded smem row stride for C1 arrays (16B-aligned rows)
#define S2   132    // padded smem row stride for C2 arrays (16B-aligned rows)
#define ECH  384
#define NTH  512    // 2 clouds per block, 256 threads each

// ---- shared (block-common) smem layout, float words ----
#define OFF_W2   0                          // 128*128 = 16384
#define OFF_W1   (OFF_W2 + 16384)           // 384
#define OFF_B1   (OFF_W1 + 384)             // 64
#define OFF_G1   (OFF_B1 + 64)
#define OFF_BE1  (OFF_G1 + 64)
#define OFF_B2   (OFF_BE1 + 64)             // 128
#define OFF_G2   (OFF_B2 + 128)
#define OFF_BE2  (OFF_G2 + 128)
#define SHARED_WORDS (OFF_BE2 + 128)        // 17344

// ---- per-group (per-cloud) smem layout, float words ----
#define GP_P2   0                           // 32*132 = 4224
#define GP_Q2   (GP_P2 + 4224)
#define GP_P1   (GP_Q2 + 4224)              // 32*68 = 2176  (F2 aliases here: 4224 <= 4352)
#define GP_Q1   (GP_P1 + 2176)
#define GP_F1   (GP_Q1 + 2176)
#define GP_XS   (GP_F1 + 2176)              // 96
#define GP_IDX  (GP_XS + 96)                // 256 ints
#define GRP_WORDS (GP_IDX + 256)            // 15328

#define SMEM1_WORDS (SHARED_WORDS + 2 * GRP_WORDS)   // 48000
#define SMEM1_BYTES (SMEM1_WORDS * 4)                // 192000

#define SMEM2_BYTES ((64*128 + 128*64) * 4)          // 65536

__device__ float g_pool[NC * C2];

__device__ __forceinline__ float elu_f(float x) {
    return x > 0.f ? x : (__expf(x) - 1.f);
}

// Edge phase: for each of 256 edges (i,k), t_j = U[i][j] + V[nbr][j]
// (bias folded into U). LayerNorm over j, ELU, max over the 8 edges of
// each point i (8 consecutive lanes), leader writes F[i][:].
template<int NCH, int STRIDE>
__device__ __forceinline__ void edge_phase(
    const float* __restrict__ U, const float* __restrict__ V,
    float* __restrict__ F, const float* __restrict__ g,
    const float* __restrict__ be, const int* __restrict__ idxs,
    float invC, int ltid)
{
    const int i = ltid >> 3;
    const int k = ltid & 7;
    const int n = idxs[i * KNB + k];
    const float4* u4 = reinterpret_cast<const float4*>(U + i * STRIDE);
    const float4* v4 = reinterpret_cast<const float4*>(V + n * STRIDE);

    float s = 0.f, ss = 0.f;
#pragma unroll 8
    for (int jj = 0; jj < NCH; jj++) {
        float4 u = u4[jj], v = v4[jj];
        float t0 = u.x + v.x, t1 = u.y + v.y, t2 = u.z + v.z, t3 = u.w + v.w;
        s += (t0 + t1) + (t2 + t3);
        ss = fmaf(t0, t0, ss); ss = fmaf(t1, t1, ss);
        ss = fmaf(t2, t2, ss); ss = fmaf(t3, t3, ss);
    }
    float mu = s * invC;
    float var = fmaxf(fmaf(-mu, mu, ss * invC), 0.f);
    float rstd = rsqrtf(var + 1e-5f);

    const float4* g4 = reinterpret_cast<const float4*>(g);
    const float4* be4 = reinterpret_cast<const float4*>(be);
    float4* Fo = reinterpret_cast<float4*>(F + i * STRIDE);

#pragma unroll 8
    for (int jj = 0; jj < NCH; jj++) {
        float4 u = u4[jj], v = v4[jj];
        float4 gg = g4[jj], bb = be4[jj];
        float e0 = elu_f(fmaf((u.x + v.x - mu) * rstd, gg.x, bb.x));
        float e1 = elu_f(fmaf((u.y + v.y - mu) * rstd, gg.y, bb.y));
        float e2 = elu_f(fmaf((u.z + v.z - mu) * rstd, gg.z, bb.z));
        float e3 = elu_f(fmaf((u.w + v.w - mu) * rstd, gg.w, bb.w));
#pragma unroll
        for (int off = 1; off < 8; off <<= 1) {
            e0 = fmaxf(e0, __shfl_xor_sync(0xffffffffu, e0, off));
            e1 = fmaxf(e1, __shfl_xor_sync(0xffffffffu, e1, off));
            e2 = fmaxf(e2, __shfl_xor_sync(0xffffffffu, e2, off));
            e3 = fmaxf(e3, __shfl_xor_sync(0xffffffffu, e3, off));
        }
        if (k == 0) Fo[jj] = make_float4(e0, e1, e2, e3);
    }
}

__global__ __launch_bounds__(NTH, 1)
void knn_encoder_kernel(
    const float* __restrict__ x,
    const float* __restrict__ W1, const float* __restrict__ b1,
    const float* __restrict__ g1, const float* __restrict__ be1,
    const float* __restrict__ W2, const float* __restrict__ b2,
    const float* __restrict__ g2, const float* __restrict__ be2)
{
    extern __shared__ float sm[];
    const int tid = threadIdx.x;
    const int gid = tid >> 8;          // cloud group 0/1 within block
    const int ltid = tid & 255;        // thread within group
    const int cloud = blockIdx.x * 2 + gid;

    float* gp = sm + SHARED_WORDS + gid * GRP_WORDS;
    int* idxs = reinterpret_cast<int*>(gp + GP_IDX);
    const float* xg = x + cloud * NP * 3;

    // ---- shared params (block-common) + per-group points ----
    for (int t = tid; t < 384; t += NTH) sm[OFF_W1 + t] = W1[t];
    if (tid < 64)  { sm[OFF_B1 + tid] = b1[tid]; sm[OFF_G1 + tid] = g1[tid]; sm[OFF_BE1 + tid] = be1[tid]; }
    if (tid < 128) { sm[OFF_B2 + tid] = b2[tid]; sm[OFF_G2 + tid] = g2[tid]; sm[OFF_BE2 + tid] = be2[tid]; }
    if (ltid < 96) gp[GP_XS + ltid] = xg[ltid];

    // ---- W2 -> smem, one copy shared by both clouds ----
    {
        const float4* src = reinterpret_cast<const float4*>(W2);
        float4* dst = reinterpret_cast<float4*>(sm + OFF_W2);
#pragma unroll
        for (int r = 0; r < 8; r++) dst[tid + r * NTH] = src[tid + r * NTH];
    }
    __syncthreads();

    // ---- KNN: warp w (within group) handles points {w, w+8, w+16, w+24}; lane = candidate m ----
    {
        const int w = ltid >> 5, m = ltid & 31;
        const float xm0 = gp[GP_XS + m * 3 + 0];
        const float xm1 = gp[GP_XS + m * 3 + 1];
        const float xm2 = gp[GP_XS + m * 3 + 2];
        const float smq = xm0 * xm0 + xm1 * xm1 + xm2 * xm2;
#pragma unroll
        for (int rep = 0; rep < 4; rep++) {
            const int i = w + rep * 8;
            const float xi0 = gp[GP_XS + i * 3 + 0];
            const float xi1 = gp[GP_XS + i * 3 + 1];
            const float xi2 = gp[GP_XS + i * 3 + 2];
            const float si = xi0 * xi0 + xi1 * xi1 + xi2 * xi2;
            const float dot = xi0 * xm0 + xi1 * xm1 + xi2 * xm2;
            float d2 = si + smq - 2.f * dot;
            for (int r = 0; r < KNB; r++) {
                float v = d2; int mi = m;
#pragma unroll
                for (int off = 16; off; off >>= 1) {
                    float ov = __shfl_xor_sync(0xffffffffu, v, off);
                    int   oi = __shfl_xor_sync(0xffffffffu, mi, off);
                    if (ov < v || (ov == v && oi < mi)) { v = ov; mi = oi; }
                }
                if (m == 0) idxs[i * KNB + r] = mi;   // lowest-index tiebreak = lax.top_k
                if (m == mi) d2 = FLT_MAX;
            }
        }
    }

    // ---- conv1 P/Q: P1[i][j] = b1[j] + x_i . W1[0:3][j], Q1[i][j] = x_i . W1[3:6][j] ----
    for (int o = ltid; o < NP * C1; o += 256) {
        const int i = o >> 6, j = o & 63;
        const float x0 = gp[GP_XS + i * 3 + 0];
        const float x1 = gp[GP_XS + i * 3 + 1];
        const float x2 = gp[GP_XS + i * 3 + 2];
        float p = sm[OFF_B1 + j];
        p = fmaf(x0, sm[OFF_W1 + j], p);
        p = fmaf(x1, sm[OFF_W1 + 64 + j], p);
        p = fmaf(x2, sm[OFF_W1 + 128 + j], p);
        float q = x0 * sm[OFF_W1 + 192 + j];
        q = fmaf(x1, sm[OFF_W1 + 256 + j], q);
        q = fmaf(x2, sm[OFF_W1 + 320 + j], q);
        gp[GP_P1 + i * S1 + j] = p;
        gp[GP_Q1 + i * S1 + j] = q;
    }
    __syncthreads();

    // ---- edge phase 1 -> f1[32][64] ----
    edge_phase<16, S1>(gp + GP_P1, gp + GP_Q1, gp + GP_F1,
                       sm + OFF_G1, sm + OFF_BE1, idxs, 1.f / 64.f, ltid);
    __syncthreads();

    // ---- conv2 P/Q GEMM: P2 = f1 @ W2[0:64] + b2, Q2 = f1 @ W2[64:128] ----
    // Per-thread tile: 4 rows (strided by 8) x 8 cols of either P or Q.
    // Warp lanes: rg 0..7 x 4 col-groups -> W reads are 4-distinct (broadcast),
    // A reads are 8-distinct banks (S1=68, row step 8 -> 8*68 mod 32 spread via rg step 68 mod 32 = 4).
    {
        const int rg = ltid & 7;           // row within stride group
        const int cg = ltid >> 3;          // 0..31 col group; >=16 -> Q
        const int j0 = (cg & 15) * 8;
        const bool isQ = (cg & 16) != 0;
        const float* Wb = sm + OFF_W2 + (isQ ? 64 * 128 : 0) + j0;
        const float* F1 = gp + GP_F1;
        float acc[4][8];
#pragma unroll
        for (int r = 0; r < 4; r++)
#pragma unroll
            for (int jj = 0; jj < 8; jj++) acc[r][jj] = 0.f;

#pragma unroll 4
        for (int c = 0; c < 64; c++) {
            float w[8];
            *reinterpret_cast<float4*>(w)     = *reinterpret_cast<const float4*>(Wb + c * 128);
            *reinterpret_cast<float4*>(w + 4) = *reinterpret_cast<const float4*>(Wb + c * 128 + 4);
            float a[4];
#pragma unroll
            for (int r = 0; r < 4; r++) a[r] = F1[(rg + r * 8) * S1 + c];
#pragma unroll
            for (int r = 0; r < 4; r++)
#pragma unroll
                for (int jj = 0; jj < 8; jj++)
                    acc[r][jj] = fmaf(a[r], w[jj], acc[r][jj]);
        }

        float* Ob = gp + (isQ ? GP_Q2 : GP_P2);
        float badd[8];
#pragma unroll
        for (int jj = 0; jj < 8; jj++) badd[jj] = isQ ? 0.f : sm[OFF_B2 + j0 + jj];
#pragma unroll
        for (int r = 0; r < 4; r++) {
            const int row = rg + r * 8;
            float4 o0 = make_float4(acc[r][0] + badd[0], acc[r][1] + badd[1],
                                    acc[r][2] + badd[2], acc[r][3] + badd[3]);
            float4 o1 = make_float4(acc[r][4] + badd[4], acc[r][5] + badd[5],
                                    acc[r][6] + badd[6], acc[r][7] + badd[7]);
            *reinterpret_cast<float4*>(Ob + row * S2 + j0)     = o0;
            *reinterpret_cast<float4*>(Ob + row * S2 + j0 + 4) = o1;
        }
    }
    __syncthreads();

    // ---- edge phase 2 -> f2[32][128], written into the dead P1/Q1 region ----
    edge_phase<32, S2>(gp + GP_P2, gp + GP_Q2, gp + GP_P1,
                       sm + OFF_G2, sm + OFF_BE2, idxs, 1.f / 128.f, ltid);
    __syncthreads();

    // ---- mean pool over points -> g_pool[cloud][128] ----
    if (ltid < 128) {
        const float* F2 = gp + GP_P1;
        float s = 0.f;
#pragma unroll 8
        for (int i = 0; i < NP; i++) s += F2[i * S2 + ltid];
        g_pool[cloud * C2 + ltid] = s * (1.f / 32.f);
    }
}

// out[4096,384] = g_pool[4096,128] @ Wo[128,384] + bo
// 64x64 output tile per block, 64KB smem -> 3 CTAs/SM.
__global__ __launch_bounds__(256)
void proj_kernel(const float* __restrict__ Wo, const float* __restrict__ bo,
                 float* __restrict__ out)
{
    extern __shared__ float sm2[];
    float* As = sm2;            // 64 x 128
    float* Ws = sm2 + 64 * 128; // 128 x 64
    const int tid = threadIdx.x;
    const int row0 = blockIdx.x * 64;
    const int colB = blockIdx.y * 64;

    {
        const float4* ag = reinterpret_cast<const float4*>(g_pool + row0 * 128);
        float4* ad = reinterpret_cast<float4*>(As);
#pragma unroll
        for (int r = 0; r < 8; r++) ad[tid + r * 256] = ag[tid + r * 256];
    }
    for (int t = tid; t < 128 * 64; t += 256) {
        const int c = t >> 6, j = t & 63;
        Ws[t] = Wo[c * ECH + colB + j];
    }
    __syncthreads();

    const int r0 = (tid >> 4) * 4;
    const int c0 = (tid & 15) * 4;
    float acc[4][4];
#pragma unroll
    for (int r = 0; r < 4; r++)
#pragma unroll
        for (int cc = 0; cc < 4; cc++) acc[r][cc] = 0.f;

#pragma unroll 4
    for (int c = 0; c < 128; c++) {
        float a[4];
#pragma unroll
        for (int r = 0; r < 4; r++) a[r] = As[(r0 + r) * 128 + c];
        float w[4];
        *reinterpret_cast<float4*>(w) = *reinterpret_cast<const float4*>(Ws + c * 64 + c0);
#pragma unroll
        for (int r = 0; r < 4; r++)
#pragma unroll
            for (int cc = 0; cc < 4; cc++)
                acc[r][cc] = fmaf(a[r], w[cc], acc[r][cc]);
    }

    float4 bb = *reinterpret_cast<const float4*>(bo + colB + c0);
#pragma unroll
    for (int r = 0; r < 4; r++) {
        float4 o = make_float4(acc[r][0] + bb.x, acc[r][1] + bb.y,
                               acc[r][2] + bb.z, acc[r][3] + bb.w);
        *reinterpret_cast<float4*>(out + (row0 + r0 + r) * ECH + colB + c0) = o;
    }
}

extern "C" void kernel_launch(void* const* d_in, const int* in_sizes, int n_in,
                              void* d_out, int out_size)
{
    const float* x   = (const float*)d_in[0];
    const float* W1  = (const float*)d_in[1];
    const float* b1  = (const float*)d_in[2];
    const float* g1  = (const float*)d_in[3];
    const float* be1 = (const float*)d_in[4];
    const float* W2  = (const float*)d_in[5];
    const float* b2  = (const float*)d_in[6];
    const float* g2  = (const float*)d_in[7];
    const float* be2 = (const float*)d_in[8];
    const float* Wo  = (const float*)d_in[9];
    const float* bo  = (const float*)d_in[10];
    float* out = (float*)d_out;

    cudaFuncSetAttribute(knn_encoder_kernel,
                         cudaFuncAttributeMaxDynamicSharedMemorySize, SMEM1_BYTES);
    cudaFuncSetAttribute(proj_kernel,
                         cudaFuncAttributeMaxDynamicSharedMemorySize, SMEM2_BYTES);

    knn_encoder_kernel<<<NC / 2, NTH, SMEM1_BYTES>>>(x, W1, b1, g1, be1, W2, b2, g2, be2);
    proj_kernel<<<dim3(NC / 64, ECH / 64), 256, SMEM2_BYTES>>>(Wo, bo, out);
}

// round 3
// speedup vs baseline: 2.5056x; 1.4319x over previous
#include <cuda_runtime.h>
#include <math.h>
#include <float.h>

#define NC   4096   // number of clouds (8*512)
#define NP   32     // points per cloud
#define KNB  8      // neighbors
#define C1   64
#define C2   128
#define S1   68     // padded smem row stride for C1 arrays
#define S2   132    // padded smem row stride for C2 arrays
#define ECH  384
#define NGRP 3      // clouds per block
#define NTH  (NGRP * 256)

// ---- shared (block-common) smem layout, float words ----
#define OFF_W2   0                          // 128*128 = 16384
#define OFF_W1   (OFF_W2 + 16384)           // 384
#define OFF_B1   (OFF_W1 + 384)             // 64
#define OFF_G1   (OFF_B1 + 64)
#define OFF_BE1  (OFF_G1 + 64)
#define OFF_B2   (OFF_BE1 + 64)             // 128
#define OFF_G2   (OFF_B2 + 128)
#define OFF_BE2  (OFF_G2 + 128)
#define SHARED_WORDS (OFF_BE2 + 128)        // 17344

// ---- per-group smem layout (words, relative) ----
// RA region (8448): phase1 holds P1@0 (32*68) and Q1@2176; after edge1 it is
// overwritten by P2@0 (32*132) and Q2@4224 (GEMM outputs).
#define GP_P1   0
#define GP_Q1   2176
#define GP_P2   0
#define GP_Q2   4224
#define GP_FB   8448                        // 2176: F1 during GEMM; warpbuf (1024) during edge2
#define GP_XS   (GP_FB + 2176)              // 96
#define GP_IDX  (GP_XS + 96)                // 256 ints
#define GRP_WORDS (GP_IDX + 256)            // 10976

#define SMEM1_WORDS (SHARED_WORDS + NGRP * GRP_WORDS)   // 50272
#define SMEM1_BYTES (SMEM1_WORDS * 4)                   // 201088

#define SMEM2_BYTES ((64*128 + 128*64) * 4)             // 65536

__device__ float g_pool[NC * C2];

__device__ __forceinline__ float elu_f(float x) {
    return x > 0.f ? x : (__expf(x) - 1.f);
}

__device__ __forceinline__ void group_bar(int gid) {
    asm volatile("bar.sync %0, %1;" :: "r"(gid + 1), "r"(256) : "memory");
}

// Transposed edge core: thread (i, s) owns channel slice [s*SLICE, s*SLICE+SLICE).
// For each neighbor k: t = U[i]+V[n_k]; per-edge LN stats reduced over the 8
// s-lanes (consecutive lanes share i); tracks z-max and z-min per channel.
template<int SLICE, int STRIDE>
__device__ __forceinline__ void edge_core(
    const float* __restrict__ U, const float* __restrict__ V,
    const int* __restrict__ idxs, float invC, int i, int s,
    float* __restrict__ zmax, float* __restrict__ zmin)
{
    float u[SLICE];
    {
        const float4* u4 = reinterpret_cast<const float4*>(U + i * STRIDE + s * SLICE);
#pragma unroll
        for (int c4 = 0; c4 < SLICE / 4; c4++)
            reinterpret_cast<float4*>(u)[c4] = u4[c4];
    }
#pragma unroll
    for (int c = 0; c < SLICE; c++) { zmax[c] = -FLT_MAX; zmin[c] = FLT_MAX; }

#pragma unroll
    for (int k = 0; k < KNB; k++) {
        const int n = idxs[i * KNB + k];
        float v[SLICE];
        {
            const float4* v4 = reinterpret_cast<const float4*>(V + n * STRIDE + s * SLICE);
#pragma unroll
            for (int c4 = 0; c4 < SLICE / 4; c4++)
                reinterpret_cast<float4*>(v)[c4] = v4[c4];
        }
        float sum = 0.f, ss = 0.f;
#pragma unroll
        for (int c = 0; c < SLICE; c++) {
            float t = u[c] + v[c];
            sum += t;
            ss = fmaf(t, t, ss);
        }
#pragma unroll
        for (int off = 1; off < 8; off <<= 1) {
            sum += __shfl_xor_sync(0xffffffffu, sum, off);
            ss  += __shfl_xor_sync(0xffffffffu, ss,  off);
        }
        const float mu = sum * invC;
        const float var = fmaxf(fmaf(-mu, mu, ss * invC), 0.f);
        const float rstd = rsqrtf(var + 1e-5f);
#pragma unroll
        for (int c = 0; c < SLICE; c++) {
            float z = (u[c] + v[c] - mu) * rstd;
            zmax[c] = fmaxf(zmax[c], z);
            zmin[c] = fminf(zmin[c], z);
        }
    }
}

__global__ __launch_bounds__(NTH, 1)
void knn_encoder_kernel(
    const float* __restrict__ x,
    const float* __restrict__ W1, const float* __restrict__ b1,
    const float* __restrict__ g1, const float* __restrict__ be1,
    const float* __restrict__ W2, const float* __restrict__ b2,
    const float* __restrict__ g2, const float* __restrict__ be2)
{
    extern __shared__ float sm[];
    const int tid = threadIdx.x;
    const int gid = tid >> 8;          // cloud group within block
    const int ltid = tid & 255;        // thread within group
    const int cloud = blockIdx.x * NGRP + gid;
    const bool live = (cloud < NC);

    float* gp = sm + SHARED_WORDS + gid * GRP_WORDS;
    int* idxs = reinterpret_cast<int*>(gp + GP_IDX);

    // ---- block-common params ----
    for (int t = tid; t < 384; t += NTH) sm[OFF_W1 + t] = W1[t];
    if (tid < 64)  { sm[OFF_B1 + tid] = b1[tid]; sm[OFF_G1 + tid] = g1[tid]; sm[OFF_BE1 + tid] = be1[tid]; }
    if (tid >= 64 && tid < 192) {
        int j = tid - 64;
        sm[OFF_B2 + j] = b2[j]; sm[OFF_G2 + j] = g2[j]; sm[OFF_BE2 + j] = be2[j];
    }
    {
        const float4* src = reinterpret_cast<const float4*>(W2);
        float4* dst = reinterpret_cast<float4*>(sm + OFF_W2);
        for (int t = tid; t < 4096; t += NTH) dst[t] = src[t];
    }
    if (live && ltid < 96) gp[GP_XS + ltid] = x[cloud * NP * 3 + ltid];
    __syncthreads();

    if (!live) return;

    // ---- KNN: warp w handles points {w, w+8, w+16, w+24}; lane = candidate m ----
    {
        const int w = ltid >> 5, m = ltid & 31;
        const float xm0 = gp[GP_XS + m * 3 + 0];
        const float xm1 = gp[GP_XS + m * 3 + 1];
        const float xm2 = gp[GP_XS + m * 3 + 2];
        const float smq = xm0 * xm0 + xm1 * xm1 + xm2 * xm2;
#pragma unroll
        for (int rep = 0; rep < 4; rep++) {
            const int i = w + rep * 8;
            const float xi0 = gp[GP_XS + i * 3 + 0];
            const float xi1 = gp[GP_XS + i * 3 + 1];
            const float xi2 = gp[GP_XS + i * 3 + 2];
            const float si = xi0 * xi0 + xi1 * xi1 + xi2 * xi2;
            const float dot = xi0 * xm0 + xi1 * xm1 + xi2 * xm2;
            float d2 = si + smq - 2.f * dot;
            for (int r = 0; r < KNB; r++) {
                float v = d2; int mi = m;
#pragma unroll
                for (int off = 16; off; off >>= 1) {
                    float ov = __shfl_xor_sync(0xffffffffu, v, off);
                    int   oi = __shfl_xor_sync(0xffffffffu, mi, off);
                    if (ov < v || (ov == v && oi < mi)) { v = ov; mi = oi; }
                }
                if (m == 0) idxs[i * KNB + r] = mi;   // lowest-index tiebreak = lax.top_k
                if (m == mi) d2 = FLT_MAX;
            }
        }
    }

    // ---- conv1 P/Q: P1[i][j] = b1[j] + x_i.W1[0:3][j], Q1[i][j] = x_i.W1[3:6][j] ----
    for (int o = ltid; o < NP * C1; o += 256) {
        const int i = o >> 6, j = o & 63;
        const float x0 = gp[GP_XS + i * 3 + 0];
        const float x1 = gp[GP_XS + i * 3 + 1];
        const float x2 = gp[GP_XS + i * 3 + 2];
        float p = sm[OFF_B1 + j];
        p = fmaf(x0, sm[OFF_W1 + j], p);
        p = fmaf(x1, sm[OFF_W1 + 64 + j], p);
        p = fmaf(x2, sm[OFF_W1 + 128 + j], p);
        float q = x0 * sm[OFF_W1 + 192 + j];
        q = fmaf(x1, sm[OFF_W1 + 256 + j], q);
        q = fmaf(x2, sm[OFF_W1 + 320 + j], q);
        gp[GP_P1 + i * S1 + j] = p;
        gp[GP_Q1 + i * S1 + j] = q;
    }
    group_bar(gid);

    // ---- edge phase 1: (i,s) slice of 8 channels -> F1[32][64] ----
    {
        const int i = ltid >> 3, s = ltid & 7;
        float zmax[8], zmin[8];
        edge_core<8, S1>(gp + GP_P1, gp + GP_Q1, idxs, 1.f / 64.f, i, s, zmax, zmin);
        float* F1 = gp + GP_FB;
        float o[8];
#pragma unroll
        for (int c = 0; c < 8; c++) {
            const int ch = s * 8 + c;
            const float gv = sm[OFF_G1 + ch], bv = sm[OFF_BE1 + ch];
            const float zs = gv > 0.f ? zmax[c] : zmin[c];
            o[c] = elu_f(fmaf(gv, zs, bv));
        }
        group_bar(gid);   // P1/Q1 reads done before GEMM overwrites RA; F1 writes after
        *reinterpret_cast<float4*>(F1 + i * S1 + s * 8)     = *reinterpret_cast<float4*>(o);
        *reinterpret_cast<float4*>(F1 + i * S1 + s * 8 + 4) = *reinterpret_cast<float4*>(o + 4);
    }
    group_bar(gid);

    // ---- conv2 P/Q GEMM: P2 = f1 @ W2[0:64] + b2, Q2 = f1 @ W2[64:128] ----
    {
        const int rg = ltid & 7;           // row within stride group
        const int cg = ltid >> 3;          // 0..31 col group; >=16 -> Q
        const int j0 = (cg & 15) * 8;
        const bool isQ = (cg & 16) != 0;
        const float* Wb = sm + OFF_W2 + (isQ ? 64 * 128 : 0) + j0;
        const float* F1 = gp + GP_FB;
        float acc[4][8];
#pragma unroll
        for (int r = 0; r < 4; r++)
#pragma unroll
            for (int jj = 0; jj < 8; jj++) acc[r][jj] = 0.f;

#pragma unroll 4
        for (int c = 0; c < 64; c++) {
            float w[8];
            *reinterpret_cast<float4*>(w)     = *reinterpret_cast<const float4*>(Wb + c * 128);
            *reinterpret_cast<float4*>(w + 4) = *reinterpret_cast<const float4*>(Wb + c * 128 + 4);
            float a[4];
#pragma unroll
            for (int r = 0; r < 4; r++) a[r] = F1[(rg + r * 8) * S1 + c];
#pragma unroll
            for (int r = 0; r < 4; r++)
#pragma unroll
                for (int jj = 0; jj < 8; jj++)
                    acc[r][jj] = fmaf(a[r], w[jj], acc[r][jj]);
        }

        float* Ob = gp + (isQ ? GP_Q2 : GP_P2);
        float badd[8];
#pragma unroll
        for (int jj = 0; jj < 8; jj++) badd[jj] = isQ ? 0.f : sm[OFF_B2 + j0 + jj];
#pragma unroll
        for (int r = 0; r < 4; r++) {
            const int row = rg + r * 8;
            float4 o0 = make_float4(acc[r][0] + badd[0], acc[r][1] + badd[1],
                                    acc[r][2] + badd[2], acc[r][3] + badd[3]);
            float4 o1 = make_float4(acc[r][4] + badd[4], acc[r][5] + badd[5],
                                    acc[r][6] + badd[6], acc[r][7] + badd[7]);
            *reinterpret_cast<float4*>(Ob + row * S2 + j0)     = o0;
            *reinterpret_cast<float4*>(Ob + row * S2 + j0 + 4) = o1;
        }
    }
    group_bar(gid);   // P2/Q2 visible; F1 reads done (warpbuf may overwrite)

    // ---- edge phase 2: (i,s) slice of 16 channels; fused pooling ----
    {
        const int i = ltid >> 3, s = ltid & 7;
        float zmax[16], zmin[16];
        edge_core<16, S2>(gp + GP_P2, gp + GP_Q2, idxs, 1.f / 128.f, i, s, zmax, zmin);
        float acc[16];
#pragma unroll
        for (int c = 0; c < 16; c++) {
            const int ch = s * 16 + c;
            const float gv = sm[OFF_G2 + ch], bv = sm[OFF_BE2 + ch];
            const float zs = gv > 0.f ? zmax[c] : zmin[c];
            acc[c] = elu_f(fmaf(gv, zs, bv));
        }
        // sum over the warp's 4 points (lanes differing in bits 3,4 share s)
#pragma unroll
        for (int c = 0; c < 16; c++) {
            acc[c] += __shfl_xor_sync(0xffffffffu, acc[c], 8);
            acc[c] += __shfl_xor_sync(0xffffffffu, acc[c], 16);
        }
        float* wb = gp + GP_FB;            // warpbuf[8][128], aliases F1
        const int w = ltid >> 5;
        if ((ltid & 24) == 0) {            // one lane per (w, s)
#pragma unroll
            for (int c4 = 0; c4 < 4; c4++)
                *reinterpret_cast<float4*>(wb + w * 128 + s * 16 + c4 * 4) =
                    *reinterpret_cast<float4*>(acc + c4 * 4);
        }
    }
    group_bar(gid);

    // ---- final pool: mean over 32 points -> g_pool[cloud][128] ----
    if (ltid < 128) {
        const float* wb = gp + GP_FB;
        float s = 0.f;
#pragma unroll
        for (int w = 0; w < 8; w++) s += wb[w * 128 + ltid];
        g_pool[cloud * C2 + ltid] = s * (1.f / 32.f);
    }
}

// out[4096,384] = g_pool[4096,128] @ Wo[128,384] + bo
__global__ __launch_bounds__(256)
void proj_kernel(const float* __restrict__ Wo, const float* __restrict__ bo,
                 float* __restrict__ out)
{
    extern __shared__ float sm2[];
    float* As = sm2;            // 64 x 128
    float* Ws = sm2 + 64 * 128; // 128 x 64
    const int tid = threadIdx.x;
    const int row0 = blockIdx.x * 64;
    const int colB = blockIdx.y * 64;

    {
        const float4* ag = reinterpret_cast<const float4*>(g_pool + row0 * 128);
        float4* ad = reinterpret_cast<float4*>(As);
#pragma unroll
        for (int r = 0; r < 8; r++) ad[tid + r * 256] = ag[tid + r * 256];
    }
    for (int t = tid; t < 128 * 64; t += 256) {
        const int c = t >> 6, j = t & 63;
        Ws[t] = Wo[c * ECH + colB + j];
    }
    __syncthreads();

    const int r0 = (tid >> 4) * 4;
    const int c0 = (tid & 15) * 4;
    float acc[4][4];
#pragma unroll
    for (int r = 0; r < 4; r++)
#pragma unroll
        for (int cc = 0; cc < 4; cc++) acc[r][cc] = 0.f;

#pragma unroll 4
    for (int c = 0; c < 128; c++) {
        float a[4];
#pragma unroll
        for (int r = 0; r < 4; r++) a[r] = As[(r0 + r) * 128 + c];
        float w[4];
        *reinterpret_cast<float4*>(w) = *reinterpret_cast<const float4*>(Ws + c * 64 + c0);
#pragma unroll
        for (int r = 0; r < 4; r++)
#pragma unroll
            for (int cc = 0; cc < 4; cc++)
                acc[r][cc] = fmaf(a[r], w[cc], acc[r][cc]);
    }

    float4 bb = *reinterpret_cast<const float4*>(bo + colB + c0);
#pragma unroll
    for (int r = 0; r < 4; r++) {
        float4 o = make_float4(acc[r][0] + bb.x, acc[r][1] + bb.y,
                               acc[r][2] + bb.z, acc[r][3] + bb.w);
        *reinterpret_cast<float4*>(out + (row0 + r0 + r) * ECH + colB + c0) = o;
    }
}

extern "C" void kernel_launch(void* const* d_in, const int* in_sizes, int n_in,
                              void* d_out, int out_size)
{
    const float* x   = (const float*)d_in[0];
    const float* W1  = (const float*)d_in[1];
    const float* b1  = (const float*)d_in[2];
    const float* g1  = (const float*)d_in[3];
    const float* be1 = (const float*)d_in[4];
    const float* W2  = (const float*)d_in[5];
    const float* b2  = (const float*)d_in[6];
    const float* g2  = (const float*)d_in[7];
    const float* be2 = (const float*)d_in[8];
    const float* Wo  = (const float*)d_in[9];
    const float* bo  = (const float*)d_in[10];
    float* out = (float*)d_out;

    cudaFuncSetAttribute(knn_encoder_kernel,
                         cudaFuncAttributeMaxDynamicSharedMemorySize, SMEM1_BYTES);
    cudaFuncSetAttribute(proj_kernel,
                         cudaFuncAttributeMaxDynamicSharedMemorySize, SMEM2_BYTES);

    knn_encoder_kernel<<<(NC + NGRP - 1) / NGRP, NTH, SMEM1_BYTES>>>(
        x, W1, b1, g1, be1, W2, b2, g2, be2);
    proj_kernel<<<dim3(NC / 64, ECH / 64), 256, SMEM2_BYTES>>>(Wo, bo, out);
}

// round 4
// speedup vs baseline: 2.5699x; 1.0256x over previous
#include <cuda_runtime.h>
#include <math.h>
#include <float.h>

#define NC   4096   // number of clouds (8*512)
#define NP   32     // points per cloud
#define KNB  8      // neighbors
#define C1   64
#define C2   128
#define S1   68     // padded smem row stride for C1 arrays
#define S2   132    // padded smem row stride for C2 arrays
#define ECH  384
#define NGRP 3      // clouds per block
#define NTH  (NGRP * 256)

typedef unsigned long long ull;

// ---- shared (block-common) smem layout, float words ----
#define OFF_W2   0                          // 128*128 = 16384
#define OFF_W1   (OFF_W2 + 16384)           // 384
#define OFF_B1   (OFF_W1 + 384)             // 64
#define OFF_G1   (OFF_B1 + 64)
#define OFF_BE1  (OFF_G1 + 64)
#define OFF_B2   (OFF_BE1 + 64)             // 128
#define OFF_G2   (OFF_B2 + 128)
#define OFF_BE2  (OFF_G2 + 128)
#define SHARED_WORDS (OFF_BE2 + 128)        // 17344

// ---- per-group smem layout (words, relative) ----
#define GP_P1   0
#define GP_Q1   2176
#define GP_P2   0
#define GP_Q2   4224
#define GP_FB   8448                        // F1 during GEMM; warpbuf during edge2
#define GP_XS   (GP_FB + 2176)              // 96
#define GP_IDX  (GP_XS + 96)                // 256 ints
#define GRP_WORDS (GP_IDX + 256)            // 10976

#define SMEM1_WORDS (SHARED_WORDS + NGRP * GRP_WORDS)   // 50272
#define SMEM1_BYTES (SMEM1_WORDS * 4)                   // 201088

#define SMEM2_BYTES ((64*128 + 128*64) * 4)             // 65536

__device__ float g_pool[NC * C2];

// ---- packed f32x2 helpers (Blackwell FFMA2 path) ----
__device__ __forceinline__ ull pk2(float lo, float hi) {
    ull r; asm("mov.b64 %0, {%1, %2};" : "=l"(r) : "f"(lo), "f"(hi)); return r;
}
__device__ __forceinline__ void upk2(ull v, float& lo, float& hi) {
    asm("mov.b64 {%0, %1}, %2;" : "=f"(lo), "=f"(hi) : "l"(v));
}
__device__ __forceinline__ ull fma2(ull a, ull b, ull c) {
    ull d; asm("fma.rn.f32x2 %0, %1, %2, %3;" : "=l"(d) : "l"(a), "l"(b), "l"(c)); return d;
}
__device__ __forceinline__ ull add2(ull a, ull b) {
    ull d; asm("add.rn.f32x2 %0, %1, %2;" : "=l"(d) : "l"(a), "l"(b)); return d;
}

__device__ __forceinline__ float elu_f(float x) {
    return x > 0.f ? x : (__expf(x) - 1.f);
}

__device__ __forceinline__ void group_bar(int gid) {
    asm volatile("bar.sync %0, %1;" :: "r"(gid + 1), "r"(256) : "memory");
}

// Transposed edge core, packed arithmetic. Thread (i, s) owns channel slice
// [s*SLICE, (s+1)*SLICE). Per neighbor: t = U[i]+V[n]; LN stats reduced over
// the 8 s-lanes; tracks per-channel z-max and z-min (scalar).
template<int SLICE, int STRIDE>
__device__ __forceinline__ void edge_core(
    const float* __restrict__ U, const float* __restrict__ V,
    const int* __restrict__ idxs, float invC, int i, int s,
    float* __restrict__ zmax, float* __restrict__ zmin)
{
    constexpr int P = SLICE / 2;       // f32x2 pairs
    ull u[P];
    {
        const ulonglong2* u2 = reinterpret_cast<const ulonglong2*>(U + i * STRIDE + s * SLICE);
#pragma unroll
        for (int q = 0; q < P / 2; q++) { ulonglong2 t = u2[q]; u[2*q] = t.x; u[2*q+1] = t.y; }
    }
#pragma unroll
    for (int c = 0; c < SLICE; c++) { zmax[c] = -FLT_MAX; zmin[c] = FLT_MAX; }

#pragma unroll
    for (int k = 0; k < KNB; k++) {
        const int n = idxs[i * KNB + k];
        const ulonglong2* v2 = reinterpret_cast<const ulonglong2*>(V + n * STRIDE + s * SLICE);
        ull t[P];
        ull sum2 = 0ULL, ss2 = 0ULL;
#pragma unroll
        for (int q = 0; q < P / 2; q++) {
            ulonglong2 vv = v2[q];
            ull t0 = add2(u[2*q], vv.x);
            ull t1 = add2(u[2*q+1], vv.y);
            t[2*q] = t0; t[2*q+1] = t1;
            sum2 = add2(sum2, t0); sum2 = add2(sum2, t1);
            ss2 = fma2(t0, t0, ss2); ss2 = fma2(t1, t1, ss2);
        }
        float sl, sh, ql, qh;
        upk2(sum2, sl, sh); upk2(ss2, ql, qh);
        float sum = sl + sh, ss = ql + qh;
#pragma unroll
        for (int off = 1; off < 8; off <<= 1) {
            sum += __shfl_xor_sync(0xffffffffu, sum, off);
            ss  += __shfl_xor_sync(0xffffffffu, ss,  off);
        }
        const float mu = sum * invC;
        const float var = fmaxf(fmaf(-mu, mu, ss * invC), 0.f);
        const float rstd = rsqrtf(var + 1e-5f);
        const ull rr = pk2(rstd, rstd);
        const float nm = -mu * rstd;
        const ull nn = pk2(nm, nm);
#pragma unroll
        for (int p = 0; p < P; p++) {
            ull z2 = fma2(t[p], rr, nn);
            float zl, zh; upk2(z2, zl, zh);
            zmax[2*p]   = fmaxf(zmax[2*p],   zl);
            zmin[2*p]   = fminf(zmin[2*p],   zl);
            zmax[2*p+1] = fmaxf(zmax[2*p+1], zh);
            zmin[2*p+1] = fminf(zmin[2*p+1], zh);
        }
    }
}

__global__ __launch_bounds__(NTH, 1)
void knn_encoder_kernel(
    const float* __restrict__ x,
    const float* __restrict__ W1, const float* __restrict__ b1,
    const float* __restrict__ g1, const float* __restrict__ be1,
    const float* __restrict__ W2, const float* __restrict__ b2,
    const float* __restrict__ g2, const float* __restrict__ be2)
{
    extern __shared__ float sm[];
    const int tid = threadIdx.x;
    const int gid = tid >> 8;
    const int ltid = tid & 255;
    const int cloud = blockIdx.x * NGRP + gid;
    const bool live = (cloud < NC);

    float* gp = sm + SHARED_WORDS + gid * GRP_WORDS;
    int* idxs = reinterpret_cast<int*>(gp + GP_IDX);

    // ---- block-common params ----
    for (int t = tid; t < 384; t += NTH) sm[OFF_W1 + t] = W1[t];
    if (tid < 64)  { sm[OFF_B1 + tid] = b1[tid]; sm[OFF_G1 + tid] = g1[tid]; sm[OFF_BE1 + tid] = be1[tid]; }
    if (tid >= 64 && tid < 192) {
        int j = tid - 64;
        sm[OFF_B2 + j] = b2[j]; sm[OFF_G2 + j] = g2[j]; sm[OFF_BE2 + j] = be2[j];
    }
    {
        const float4* src = reinterpret_cast<const float4*>(W2);
        float4* dst = reinterpret_cast<float4*>(sm + OFF_W2);
        for (int t = tid; t < 4096; t += NTH) dst[t] = src[t];
    }
    if (live && ltid < 96) gp[GP_XS + ltid] = x[cloud * NP * 3 + ltid];
    __syncthreads();

    if (!live) return;

    // ---- KNN ----
    {
        const int w = ltid >> 5, m = ltid & 31;
        const float xm0 = gp[GP_XS + m * 3 + 0];
        const float xm1 = gp[GP_XS + m * 3 + 1];
        const float xm2 = gp[GP_XS + m * 3 + 2];
        const float smq = xm0 * xm0 + xm1 * xm1 + xm2 * xm2;
#pragma unroll
        for (int rep = 0; rep < 4; rep++) {
            const int i = w + rep * 8;
            const float xi0 = gp[GP_XS + i * 3 + 0];
            const float xi1 = gp[GP_XS + i * 3 + 1];
            const float xi2 = gp[GP_XS + i * 3 + 2];
            const float si = xi0 * xi0 + xi1 * xi1 + xi2 * xi2;
            const float dot = xi0 * xm0 + xi1 * xm1 + xi2 * xm2;
            float d2 = si + smq - 2.f * dot;
            for (int r = 0; r < KNB; r++) {
                float v = d2; int mi = m;
#pragma unroll
                for (int off = 16; off; off >>= 1) {
                    float ov = __shfl_xor_sync(0xffffffffu, v, off);
                    int   oi = __shfl_xor_sync(0xffffffffu, mi, off);
                    if (ov < v || (ov == v && oi < mi)) { v = ov; mi = oi; }
                }
                if (m == 0) idxs[i * KNB + r] = mi;
                if (m == mi) d2 = FLT_MAX;
            }
        }
    }

    // ---- conv1 P/Q ----
    for (int o = ltid; o < NP * C1; o += 256) {
        const int i = o >> 6, j = o & 63;
        const float x0 = gp[GP_XS + i * 3 + 0];
        const float x1 = gp[GP_XS + i * 3 + 1];
        const float x2 = gp[GP_XS + i * 3 + 2];
        float p = sm[OFF_B1 + j];
        p = fmaf(x0, sm[OFF_W1 + j], p);
        p = fmaf(x1, sm[OFF_W1 + 64 + j], p);
        p = fmaf(x2, sm[OFF_W1 + 128 + j], p);
        float q = x0 * sm[OFF_W1 + 192 + j];
        q = fmaf(x1, sm[OFF_W1 + 256 + j], q);
        q = fmaf(x2, sm[OFF_W1 + 320 + j], q);
        gp[GP_P1 + i * S1 + j] = p;
        gp[GP_Q1 + i * S1 + j] = q;
    }
    group_bar(gid);

    // ---- edge phase 1 -> F1[32][64] ----
    {
        const int i = ltid >> 3, s = ltid & 7;
        float zmax[8], zmin[8];
        edge_core<8, S1>(gp + GP_P1, gp + GP_Q1, idxs, 1.f / 64.f, i, s, zmax, zmin);
        float* F1 = gp + GP_FB;
        float o[8];
#pragma unroll
        for (int c = 0; c < 8; c++) {
            const int ch = s * 8 + c;
            const float gv = sm[OFF_G1 + ch], bv = sm[OFF_BE1 + ch];
            const float zs = gv > 0.f ? zmax[c] : zmin[c];
            o[c] = elu_f(fmaf(gv, zs, bv));
        }
        group_bar(gid);
        *reinterpret_cast<float4*>(F1 + i * S1 + s * 8)     = *reinterpret_cast<float4*>(o);
        *reinterpret_cast<float4*>(F1 + i * S1 + s * 8 + 4) = *reinterpret_cast<float4*>(o + 4);
    }
    group_bar(gid);

    // ---- conv2 P/Q GEMM (packed FFMA2): P2 = f1@W2[0:64]+b2, Q2 = f1@W2[64:128] ----
    {
        const int rg = ltid & 7;
        const int cg = ltid >> 3;
        const int j0 = (cg & 15) * 8;
        const bool isQ = (cg & 16) != 0;
        const float* Wb = sm + OFF_W2 + (isQ ? 64 * 128 : 0) + j0;
        const float* F1 = gp + GP_FB;
        ull acc[4][4];
#pragma unroll
        for (int r = 0; r < 4; r++)
#pragma unroll
            for (int p = 0; p < 4; p++) acc[r][p] = 0ULL;

#pragma unroll 4
        for (int c = 0; c < 64; c++) {
            const ulonglong2 wA = *reinterpret_cast<const ulonglong2*>(Wb + c * 128);
            const ulonglong2 wB = *reinterpret_cast<const ulonglong2*>(Wb + c * 128 + 4);
#pragma unroll
            for (int r = 0; r < 4; r++) {
                const float a = F1[(rg + r * 8) * S1 + c];
                const ull aa = pk2(a, a);
                acc[r][0] = fma2(aa, wA.x, acc[r][0]);
                acc[r][1] = fma2(aa, wA.y, acc[r][1]);
                acc[r][2] = fma2(aa, wB.x, acc[r][2]);
                acc[r][3] = fma2(aa, wB.y, acc[r][3]);
            }
        }

        float* Ob = gp + (isQ ? GP_Q2 : GP_P2);
        ull bp[4];
        if (!isQ) {
            const ulonglong2 bA = *reinterpret_cast<const ulonglong2*>(sm + OFF_B2 + j0);
            const ulonglong2 bB = *reinterpret_cast<const ulonglong2*>(sm + OFF_B2 + j0 + 4);
            bp[0] = bA.x; bp[1] = bA.y; bp[2] = bB.x; bp[3] = bB.y;
        } else {
            bp[0] = bp[1] = bp[2] = bp[3] = 0ULL;
        }
#pragma unroll
        for (int r = 0; r < 4; r++) {
            const int row = rg + r * 8;
            ulonglong2 s0, s1;
            s0.x = add2(acc[r][0], bp[0]); s0.y = add2(acc[r][1], bp[1]);
            s1.x = add2(acc[r][2], bp[2]); s1.y = add2(acc[r][3], bp[3]);
            *reinterpret_cast<ulonglong2*>(Ob + row * S2 + j0)     = s0;
            *reinterpret_cast<ulonglong2*>(Ob + row * S2 + j0 + 4) = s1;
        }
    }
    group_bar(gid);

    // ---- edge phase 2 (fused pooling) ----
    {
        const int i = ltid >> 3, s = ltid & 7;
        float zmax[16], zmin[16];
        edge_core<16, S2>(gp + GP_P2, gp + GP_Q2, idxs, 1.f / 128.f, i, s, zmax, zmin);
        float acc[16];
#pragma unroll
        for (int c = 0; c < 16; c++) {
            const int ch = s * 16 + c;
            const float gv = sm[OFF_G2 + ch], bv = sm[OFF_BE2 + ch];
            const float zs = gv > 0.f ? zmax[c] : zmin[c];
            acc[c] = elu_f(fmaf(gv, zs, bv));
        }
#pragma unroll
        for (int c = 0; c < 16; c++) {
            acc[c] += __shfl_xor_sync(0xffffffffu, acc[c], 8);
            acc[c] += __shfl_xor_sync(0xffffffffu, acc[c], 16);
        }
        float* wb = gp + GP_FB;
        const int w = ltid >> 5;
        if ((ltid & 24) == 0) {
#pragma unroll
            for (int c4 = 0; c4 < 4; c4++)
                *reinterpret_cast<float4*>(wb + w * 128 + s * 16 + c4 * 4) =
                    *reinterpret_cast<float4*>(acc + c4 * 4);
        }
    }
    group_bar(gid);

    // ---- final pool ----
    if (ltid < 128) {
        const float* wb = gp + GP_FB;
        float s = 0.f;
#pragma unroll
        for (int w = 0; w < 8; w++) s += wb[w * 128 + ltid];
        g_pool[cloud * C2 + ltid] = s * (1.f / 32.f);
    }
}

// out[4096,384] = g_pool[4096,128] @ Wo[128,384] + bo  (packed FFMA2)
__global__ __launch_bounds__(256)
void proj_kernel(const float* __restrict__ Wo, const float* __restrict__ bo,
                 float* __restrict__ out)
{
    extern __shared__ float sm2[];
    float* As = sm2;            // 64 x 128
    float* Ws = sm2 + 64 * 128; // 128 x 64
    const int tid = threadIdx.x;
    const int row0 = blockIdx.x * 64;
    const int colB = blockIdx.y * 64;

    {
        const float4* ag = reinterpret_cast<const float4*>(g_pool + row0 * 128);
        float4* ad = reinterpret_cast<float4*>(As);
#pragma unroll
        for (int r = 0; r < 8; r++) ad[tid + r * 256] = ag[tid + r * 256];
    }
    for (int t = tid; t < 128 * 64; t += 256) {
        const int c = t >> 6, j = t & 63;
        Ws[t] = Wo[c * ECH + colB + j];
    }
    __syncthreads();

    const int r0 = (tid >> 4) * 4;
    const int c0 = (tid & 15) * 4;
    ull acc[4][2];
#pragma unroll
    for (int r = 0; r < 4; r++) { acc[r][0] = 0ULL; acc[r][1] = 0ULL; }

#pragma unroll 4
    for (int c = 0; c < 128; c++) {
        const ulonglong2 w = *reinterpret_cast<const ulonglong2*>(Ws + c * 64 + c0);
#pragma unroll
        for (int r = 0; r < 4; r++) {
            const float a = As[(r0 + r) * 128 + c];
            const ull aa = pk2(a, a);
            acc[r][0] = fma2(aa, w.x, acc[r][0]);
            acc[r][1] = fma2(aa, w.y, acc[r][1]);
        }
    }

    const ulonglong2 bb = *reinterpret_cast<const ulonglong2*>(bo + colB + c0);
#pragma unroll
    for (int r = 0; r < 4; r++) {
        ulonglong2 o;
        o.x = add2(acc[r][0], bb.x);
        o.y = add2(acc[r][1], bb.y);
        *reinterpret_cast<ulonglong2*>(out + (row0 + r0 + r) * ECH + colB + c0) = o;
    }
}

extern "C" void kernel_launch(void* const* d_in, const int* in_sizes, int n_in,
                              void* d_out, int out_size)
{
    const float* x   = (const float*)d_in[0];
    const float* W1  = (const float*)d_in[1];
    const float* b1  = (const float*)d_in[2];
    const float* g1  = (const float*)d_in[3];
    const float* be1 = (const float*)d_in[4];
    const float* W2  = (const float*)d_in[5];
    const float* b2  = (const float*)d_in[6];
    const float* g2  = (const float*)d_in[7];
    const float* be2 = (const float*)d_in[8];
    const float* Wo  = (const float*)d_in[9];
    const float* bo  = (const float*)d_in[10];
    float* out = (float*)d_out;

    cudaFuncSetAttribute(knn_encoder_kernel,
                         cudaFuncAttributeMaxDynamicSharedMemorySize, SMEM1_BYTES);
    cudaFuncSetAttribute(proj_kernel,
                         cudaFuncAttributeMaxDynamicSharedMemorySize, SMEM2_BYTES);

    knn_encoder_kernel<<<(NC + NGRP - 1) / NGRP, NTH, SMEM1_BYTES>>>(
        x, W1, b1, g1, be1, W2, b2, g2, be2);
    proj_kernel<<<dim3(NC / 64, ECH / 64), 256, SMEM2_BYTES>>>(Wo, bo, out);
}